// round 16
// baseline (speedup 1.0000x reference)
#include <cuda_runtime.h>
#include <math.h>
#include <float.h>

#define BB 32
#define TT 32
#define EE 1024
#define HHH 1024
#define GG 4096
#define VV 32000
#define SS 20
#define TOPN 10

// ---------------- device scratch ----------------
__device__ __align__(16) float g_x[2 * 2 * BB * TT * EE];    // [enc][buf][B*T][E]
__device__ __align__(16) float g_z[2 * BB * TT * GG];        // [enc][B*T][4H]
__device__ __align__(16) float g_hT[2 * 2 * HHH * BB];       // [enc][parity][H][B]
__device__ __align__(16) float g_cn[2 * BB * HHH];           // [enc][B][H]
__device__ __align__(16) float g_Whp[2 * 2 * HHH * GG];      // [enc][l][k][c*4+g]
__device__ __align__(16) float g_dWp[2 * 2048 * GG];         // [l][k(0..2047)][c*4+g]
__device__ __align__(16) float g_dhT[2 * 2 * HHH * BB];      // [l][parity][H][B]
__device__ __align__(16) float g_dcn[2 * BB * HHH];          // [l][B][H]
__device__ __align__(16) float g_dxT[EE * BB];               // [E][B]
__device__ int   g_tok[BB];
__device__ float g_u[(SS - 1) * BB];
__device__ float g_tokf[BB * SS];                            // fallback token sink

__device__ __forceinline__ float sigm(float x) { return 1.0f / (1.0f + expf(-x)); }

// ---------------- threefry2x32 core (bit-exact JAX) ----------------
__device__ __forceinline__ void tf2x32(unsigned k0, unsigned k1, unsigned x0, unsigned x1,
                                       unsigned& o0, unsigned& o1)
{
    unsigned ks2 = k0 ^ k1 ^ 0x1BD11BDAu;
    x0 += k0; x1 += k1;
#define TFR(r) { x0 += x1; x1 = (x1 << (r)) | (x1 >> (32 - (r))); x1 ^= x0; }
    TFR(13) TFR(15) TFR(26) TFR(6)   x0 += k1;  x1 += ks2 + 1u;
    TFR(17) TFR(29) TFR(16) TFR(24)  x0 += ks2; x1 += k0 + 2u;
    TFR(13) TFR(15) TFR(26) TFR(6)   x0 += k0;  x1 += k1 + 3u;
    TFR(17) TFR(29) TFR(16) TFR(24)  x0 += k1;  x1 += ks2 + 4u;
    TFR(13) TFR(15) TFR(26) TFR(6)   x0 += ks2; x1 += k0 + 5u;
#undef TFR
    o0 = x0; o1 = x1;
}

// Partitionable-mode (JAX >= 0.4.30 default) key-split + 32-bit random_bits:
//   split(key,(n,)):  key_j = threefry2x32(key, (hi=0, lo=j)) -> (o0, o1)
//   random_bits(key, 32, shape): bits_i = o0 ^ o1 of threefry2x32(key, (0, i))
//   uniform = bitcast((bits >> 9) | 0x3f800000) - 1
__global__ void prep_misc_k()
{
    int t = blockIdx.x * blockDim.x + threadIdx.x;
    if (t < (SS - 1) * BB) {
        int s = t >> 5, b = t & 31;
        unsigned k0, k1;
        tf2x32(0u, 1u, 0u, (unsigned)s, k0, k1);   // key for scan step s (key(1) = (0,1))
        unsigned o0, o1;
        tf2x32(k0, k1, 0u, (unsigned)b, o0, o1);
        unsigned bits = o0 ^ o1;
        g_u[t] = __uint_as_float((bits >> 9) | 0x3f800000u) - 1.0f;
    }
}

// ---------------- weight preprocessing (gate-interleave) ----------------
__global__ void prep_encW_k(const float* __restrict__ Wh1, const float* __restrict__ Wh2)
{
    const long TOT = 2L * 2 * HHH * GG;
    for (long idx = (long)blockIdx.x * blockDim.x + threadIdx.x; idx < TOT;
         idx += (long)gridDim.x * blockDim.x) {
        int cg = (int)(idx & 4095); int c = cg >> 2, g = cg & 3;
        long r = idx >> 12;                        // enc*2048 + l*1024 + k
        int k = (int)(r & 1023); int l = (int)((r >> 10) & 1); int enc = (int)(r >> 11);
        const float* W = enc ? Wh2 : Wh1;
        g_Whp[idx] = W[((long)l * HHH + k) * GG + (long)g * HHH + c];
    }
}

__global__ void prep_decW_k(const float* __restrict__ dWx, const float* __restrict__ dWh)
{
    const long TOT = 2L * 2048 * GG;
    for (long idx = (long)blockIdx.x * blockDim.x + threadIdx.x; idx < TOT;
         idx += (long)gridDim.x * blockDim.x) {
        int cg = (int)(idx & 4095); int c = cg >> 2, g = cg & 3;
        long r = idx >> 12;                        // l*2048 + k2
        int k2 = (int)(r & 2047); int l = (int)(r >> 11);
        float v;
        if (k2 < 1024) v = dWx[((long)l * EE + k2) * GG + (long)g * HHH + c];
        else           v = dWh[((long)l * HHH + (k2 - 1024)) * GG + (long)g * HHH + c];
        g_dWp[idx] = v;
    }
}

// ---------------- encoder embedding gather ----------------
__global__ void embed_k(const int* __restrict__ tokens, const float* __restrict__ emb1,
                        const float* __restrict__ emb2)
{
    int bt = blockIdx.x, enc = blockIdx.y;
    int tok = tokens[bt];
    const float4* src = (const float4*)((enc ? emb2 : emb1) + (size_t)tok * EE);
    float4* dst = (float4*)(g_x + ((size_t)enc * 2) * (BB * TT * EE) + (size_t)bt * EE);
    dst[threadIdx.x] = src[threadIdx.x];   // 256 thr * float4 = 1024
}

__global__ void zero_enc_k()
{
    int idx = blockIdx.x * blockDim.x + threadIdx.x;    // < 65536
    if (idx < 2 * HHH * BB) {
        int enc = idx >> 15, off = idx & 32767;
        g_hT[(enc * 2 + 0) * (HHH * BB) + off] = 0.f;
        g_cn[enc * (BB * HHH) + off] = 0.f;
    }
}

// ---------------- big GEMM: z[enc] = X @ Wx + b  (M=1024,K=1024,N=4096) ----------------
__global__ void __launch_bounds__(256) gemm_bt_k(
    const float* __restrict__ Wx1, const float* __restrict__ Wx2,
    const float* __restrict__ b1, const float* __restrict__ b2, int l)
{
    const int enc = blockIdx.z;
    const float* A = g_x + ((size_t)enc * 2 + (l & 1)) * (BB * TT * EE);
    const float* W = enc ? Wx2 : Wx1;
    const float* bias = enc ? b2 : b1;
    float* C = g_z + (size_t)enc * (BB * TT * GG);
    const int K = EE, N = GG;

    __shared__ __align__(16) float As[8][132];
    __shared__ __align__(16) float Bs[8][128];
    int bm = blockIdx.y * 128, bn = blockIdx.x * 128;
    int tid = threadIdx.x;
    int ty = tid >> 4, tx = tid & 15;
    float acc[8][8];
#pragma unroll
    for (int i = 0; i < 8; i++)
#pragma unroll
        for (int j = 0; j < 8; j++) acc[i][j] = 0.f;

    int ar = tid >> 1, ac = (tid & 1) * 4;
    int br = tid >> 5, bc = (tid & 31) * 4;

    for (int k0 = 0; k0 < K; k0 += 8) {
        float4 av = *(const float4*)(A + (size_t)(bm + ar) * K + k0 + ac);
        As[ac + 0][ar] = av.x; As[ac + 1][ar] = av.y; As[ac + 2][ar] = av.z; As[ac + 3][ar] = av.w;
        *(float4*)&Bs[br][bc] = *(const float4*)(W + (size_t)(k0 + br) * N + bn + bc);
        __syncthreads();
#pragma unroll
        for (int kk = 0; kk < 8; kk++) {
            float a[8], bw[8];
            *(float4*)(a)     = *(const float4*)&As[kk][ty * 8];
            *(float4*)(a + 4) = *(const float4*)&As[kk][ty * 8 + 4];
            *(float4*)(bw)    = *(const float4*)&Bs[kk][tx * 8];
            *(float4*)(bw + 4)= *(const float4*)&Bs[kk][tx * 8 + 4];
#pragma unroll
            for (int i = 0; i < 8; i++)
#pragma unroll
                for (int j = 0; j < 8; j++) acc[i][j] = fmaf(a[i], bw[j], acc[i][j]);
        }
        __syncthreads();
    }
    float bv[8];
#pragma unroll
    for (int j = 0; j < 8; j++) bv[j] = bias[bn + tx * 8 + j];
    for (int i = 0; i < 8; i++) {
        float* crow = C + (size_t)(bm + ty * 8 + i) * N + bn + tx * 8;
#pragma unroll
        for (int j = 0; j < 8; j++) crow[j] = acc[i][j] + bv[j];
    }
}

// ---------------- encoder recurrent step (h@Wh + precomputed z, fused gates) ----------------
// grid (64, 2enc), block 128.  Tile: 16 h-cols * 4 gates, all 32 rows, K=1024.
__global__ void __launch_bounds__(128) enc_step_k(int t, int l)
{
    const int enc = blockIdx.y;
    const int c0 = blockIdx.x * 16;
    const int tid = threadIdx.x;
    const int rg = tid >> 4;        // 0..7 -> rows rg*4..+4
    const int j = tid & 15;         // h-col within tile
    const int p = t & 1;
    const int ob = (l & 1) ^ 1;

    __shared__ __align__(16) float hs[32 * 32];
    __shared__ __align__(16) float ws[32 * 64];

    float acc[4][4];
#pragma unroll
    for (int r = 0; r < 4; r++)
#pragma unroll
        for (int g = 0; g < 4; g++) acc[r][g] = 0.f;

    const float* hbase = g_hT + (size_t)(enc * 2 + p) * (HHH * BB);
    const float* wbase = g_Whp + ((size_t)(enc * 2 + l) * HHH) * GG + c0 * 4;

    for (int k0 = 0; k0 < HHH; k0 += 32) {
        const float4* hsrc = (const float4*)(hbase + k0 * BB);
        ((float4*)hs)[tid * 2]     = hsrc[tid * 2];
        ((float4*)hs)[tid * 2 + 1] = hsrc[tid * 2 + 1];
        const float* wsrc = wbase + (size_t)k0 * GG;
#pragma unroll
        for (int u = 0; u < 4; u++) {
            int idx = tid + u * 128;
            int kk = idx >> 4, cc = (idx & 15) * 4;
            *(float4*)&ws[kk * 64 + cc] = *(const float4*)&wsrc[(size_t)kk * GG + cc];
        }
        __syncthreads();
#pragma unroll
        for (int kk = 0; kk < 32; kk++) {
            float4 a4 = *(const float4*)&hs[kk * 32 + rg * 4];
            float4 w4 = *(const float4*)&ws[kk * 64 + j * 4];
            float a[4] = {a4.x, a4.y, a4.z, a4.w};
            float w[4] = {w4.x, w4.y, w4.z, w4.w};
#pragma unroll
            for (int r = 0; r < 4; r++)
#pragma unroll
                for (int g = 0; g < 4; g++) acc[r][g] = fmaf(a[r], w[g], acc[r][g]);
        }
        __syncthreads();
    }

    const float* zbase = g_z + (size_t)enc * (BB * TT * GG);
    float* hTout = g_hT + (size_t)(enc * 2 + (p ^ 1)) * (HHH * BB);
    float* xout = g_x + ((size_t)enc * 2 + ob) * (BB * TT * EE);
    float* cbase = g_cn + (size_t)enc * (BB * HHH);
    const int col = c0 + j;
#pragma unroll
    for (int r = 0; r < 4; r++) {
        int b = rg * 4 + r;
        int m = b * TT + t;
        const float* zr = zbase + (size_t)m * GG;
        float zi = zr[0 * HHH + col] + acc[r][0];
        float zf = zr[1 * HHH + col] + acc[r][1];
        float zg = zr[2 * HHH + col] + acc[r][2];
        float zo = zr[3 * HHH + col] + acc[r][3];
        float co = cbase[b * HHH + col];
        float cnw = sigm(zf) * co + sigm(zi) * tanhf(zg);
        float hn = sigm(zo) * tanhf(cnw);
        cbase[b * HHH + col] = cnw;
        hTout[col * BB + b] = hn;
        xout[(size_t)m * EE + col] = hn;
    }
}

// ---------------- blend + global L2 normalize -> decoder init states ----------------
__global__ void blend_k(int l)
{
    __shared__ float red[1024];
    __shared__ float s_inv;
    int tid = threadIdx.x;
    const int N = HHH * BB;

    // h (transposed layout, final parity 0)
    float loc = 0.f;
    for (int i = tid; i < N; i += 1024) {
        float v = g_hT[i] + 2.0f * g_hT[2 * N + i];
        loc += v * v;
    }
    red[tid] = loc; __syncthreads();
    for (int o = 512; o > 0; o >>= 1) { if (tid < o) red[tid] += red[tid + o]; __syncthreads(); }
    if (tid == 0) s_inv = 1.0f / (sqrtf(red[0]) + 1e-12f);
    __syncthreads();
    float inv = s_inv;
    for (int i = tid; i < N; i += 1024) {
        float v = g_hT[i] + 2.0f * g_hT[2 * N + i];
        g_dhT[(l * 2 + 0) * N + i] = v * inv;
    }
    __syncthreads();

    // c (normal layout)
    loc = 0.f;
    for (int i = tid; i < N; i += 1024) {
        float v = g_cn[i] + 2.0f * g_cn[N + i];
        loc += v * v;
    }
    red[tid] = loc; __syncthreads();
    for (int o = 512; o > 0; o >>= 1) { if (tid < o) red[tid] += red[tid + o]; __syncthreads(); }
    if (tid == 0) s_inv = 1.0f / (sqrtf(red[0]) + 1e-12f);
    __syncthreads();
    inv = s_inv;
    for (int i = tid; i < N; i += 1024) {
        float v = g_cn[i] + 2.0f * g_cn[N + i];
        g_dcn[l * N + i] = v * inv;
    }
}

// ---------------- decoder embedding gather (transposed) ----------------
__global__ void dembedT_k(const float* __restrict__ emb1, const int* __restrict__ start_ptr,
                          int use_start)
{
    int idx = blockIdx.x * blockDim.x + threadIdx.x;   // < 32768
    if (idx < EE * BB) {
        int b = idx & 31, k = idx >> 5;
        int tok = use_start ? (start_ptr ? start_ptr[0] : 1) : g_tok[b];
        g_dxT[k * BB + b] = emb1[(size_t)tok * EE + k];
    }
}

// ---------------- decoder LSTM cell (x@Wx + h@Wh fused, K=2048) ----------------
// grid 128, block 128.  Tile: 8 h-cols * 4 gates, rows split 16x2.
__global__ void __launch_bounds__(128) dec_cell_k(int s, int l, const float* __restrict__ bias_all)
{
    const int c0 = blockIdx.x * 8;
    const int tid = threadIdx.x;
    const int rg = tid >> 3;     // 0..15 -> rows rg*2
    const int j = tid & 7;
    const int ps = s & 1;
    const int N = HHH * BB;

    __shared__ __align__(16) float hs[32 * 32];
    __shared__ __align__(16) float ws[32 * 32];

    float acc[2][4];
#pragma unroll
    for (int r = 0; r < 2; r++)
#pragma unroll
        for (int g = 0; g < 4; g++) acc[r][g] = 0.f;

    const float* xT = (l == 0) ? g_dxT : (g_dhT + (size_t)(0 * 2 + (ps ^ 1)) * N);
    const float* hT = g_dhT + (size_t)(l * 2 + ps) * N;
    const float* wbase = g_dWp + (size_t)l * 2048 * GG + c0 * 4;

    for (int k0 = 0; k0 < 2048; k0 += 32) {
        const float* src = (k0 < 1024) ? (xT + k0 * BB) : (hT + (k0 - 1024) * BB);
        ((float4*)hs)[tid * 2]     = ((const float4*)src)[tid * 2];
        ((float4*)hs)[tid * 2 + 1] = ((const float4*)src)[tid * 2 + 1];
        const float* wsrc = wbase + (size_t)k0 * GG;
#pragma unroll
        for (int u = 0; u < 2; u++) {
            int idx = tid + u * 128;
            int kk = idx >> 3, cc = (idx & 7) * 4;
            *(float4*)&ws[kk * 32 + cc] = *(const float4*)&wsrc[(size_t)kk * GG + cc];
        }
        __syncthreads();
#pragma unroll
        for (int kk = 0; kk < 32; kk++) {
            float2 a2 = *(const float2*)&hs[kk * 32 + rg * 2];
            float4 w4 = *(const float4*)&ws[kk * 32 + j * 4];
            float w[4] = {w4.x, w4.y, w4.z, w4.w};
#pragma unroll
            for (int g = 0; g < 4; g++) {
                acc[0][g] = fmaf(a2.x, w[g], acc[0][g]);
                acc[1][g] = fmaf(a2.y, w[g], acc[1][g]);
            }
        }
        __syncthreads();
    }

    const float* bias = bias_all + (size_t)l * GG;
    float* hTout = g_dhT + (size_t)(l * 2 + (ps ^ 1)) * N;
    float* cbase = g_dcn + (size_t)l * N;
    const int col = c0 + j;
#pragma unroll
    for (int r = 0; r < 2; r++) {
        int b = rg * 2 + r;
        float zi = acc[r][0] + bias[0 * HHH + col];
        float zf = acc[r][1] + bias[1 * HHH + col];
        float zg = acc[r][2] + bias[2 * HHH + col];
        float zo = acc[r][3] + bias[3 * HHH + col];
        float co = cbase[b * HHH + col];
        float cnw = sigm(zf) * co + sigm(zi) * tanhf(zg);
        float hn = sigm(zo) * tanhf(cnw);
        cbase[b * HHH + col] = cnw;
        hTout[col * BB + b] = hn;
    }
}

// ---------------- logits GEMM: [32,1024] x [1024,32000] + bd ----------------
// grid 250, block 256.  Tile 32 x 128.
__global__ void __launch_bounds__(256) logits_k(const float* __restrict__ Wd,
                                                const float* __restrict__ bd,
                                                float* __restrict__ outlog, int s)
{
    const int n0 = blockIdx.x * 128;
    const int tid = threadIdx.x;
    const int rg = tid >> 5;     // 0..7 -> rows rg*4
    const int cg = tid & 31;     // cols cg*4

    __shared__ __align__(16) float As[32 * 32];
    __shared__ __align__(16) float Bs[32 * 128];

    const float* A = g_dhT + (size_t)(1 * 2 + ((s & 1) ^ 1)) * (HHH * BB);

    float acc[4][4];
#pragma unroll
    for (int r = 0; r < 4; r++)
#pragma unroll
        for (int c = 0; c < 4; c++) acc[r][c] = 0.f;

    for (int k0 = 0; k0 < HHH; k0 += 32) {
        ((float4*)As)[tid] = ((const float4*)(A + k0 * BB))[tid];   // 256*4 = 1024
        const float* wsrc = Wd + (size_t)k0 * VV + n0;
#pragma unroll
        for (int u = 0; u < 4; u++) {
            int idx = tid + u * 256;
            int kk = idx >> 5, cc = (idx & 31) * 4;
            *(float4*)&Bs[kk * 128 + cc] = *(const float4*)&wsrc[(size_t)kk * VV + cc];
        }
        __syncthreads();
#pragma unroll
        for (int kk = 0; kk < 32; kk++) {
            float4 a4 = *(const float4*)&As[kk * 32 + rg * 4];
            float4 b4 = *(const float4*)&Bs[kk * 128 + cg * 4];
            float a[4] = {a4.x, a4.y, a4.z, a4.w};
            float bw[4] = {b4.x, b4.y, b4.z, b4.w};
#pragma unroll
            for (int r = 0; r < 4; r++)
#pragma unroll
                for (int c = 0; c < 4; c++) acc[r][c] = fmaf(a[r], bw[c], acc[r][c]);
        }
        __syncthreads();
    }

    const int nb = n0 + cg * 4;
    float4 bv = *(const float4*)&bd[nb];
    float bwv[4] = {bv.x, bv.y, bv.z, bv.w};
#pragma unroll
    for (int r = 0; r < 4; r++) {
        int b = rg * 4 + r;
        float4 o;
        o.x = acc[r][0] + bwv[0];
        o.y = acc[r][1] + bwv[1];
        o.z = acc[r][2] + bwv[2];
        o.w = acc[r][3] + bwv[3];
        *(float4*)&outlog[((size_t)b * SS + s) * VV + nb] = o;
    }
}

// ---------------- argmax / top-10 sampling ----------------
__device__ __forceinline__ bool better(float v1, int i1, float v2, int i2)
{
    return (v1 > v2) || (v1 == v2 && i1 < i2);
}

__global__ void sample_k(const float* __restrict__ outlog, float* __restrict__ outtok, int s)
{
    const int b = blockIdx.x;
    const int tid = threadIdx.x;
    const float* lg = outlog + ((size_t)b * SS + s) * VV;

    __shared__ float rv[256];
    __shared__ int ri[256];
    __shared__ int rt[256];

    if (s == 0) {
        float bv = -FLT_MAX; int bi = 0x7fffffff;
        for (int n = tid; n < VV; n += 256) {
            float v = lg[n];
            if (better(v, n, bv, bi)) { bv = v; bi = n; }
        }
        rv[tid] = bv; ri[tid] = bi;
        __syncthreads();
        for (int o = 128; o > 0; o >>= 1) {
            if (tid < o && better(rv[tid + o], ri[tid + o], rv[tid], ri[tid])) {
                rv[tid] = rv[tid + o]; ri[tid] = ri[tid + o];
            }
            __syncthreads();
        }
        if (tid == 0) {
            g_tok[b] = ri[0];
            outtok[b * SS + 0] = (float)ri[0];
        }
        return;
    }

    __shared__ float sv[256 * TOPN];
    __shared__ int si[256 * TOPN];
    __shared__ float topv[TOPN];
    __shared__ int topi[TOPN];

    float lv[TOPN]; int li[TOPN];
#pragma unroll
    for (int k = 0; k < TOPN; k++) { lv[k] = -FLT_MAX; li[k] = 0x7fffffff; }
    for (int n = tid; n < VV; n += 256) {
        float v = lg[n];
        if (better(v, n, lv[TOPN - 1], li[TOPN - 1])) {
            int k = TOPN - 1;
            while (k > 0 && better(v, n, lv[k - 1], li[k - 1])) {
                lv[k] = lv[k - 1]; li[k] = li[k - 1]; k--;
            }
            lv[k] = v; li[k] = n;
        }
    }
#pragma unroll
    for (int k = 0; k < TOPN; k++) { sv[tid * TOPN + k] = lv[k]; si[tid * TOPN + k] = li[k]; }

    int ptr = 0;
    for (int k = 0; k < TOPN; k++) {
        float cv; int ci;
        if (ptr < TOPN) { cv = sv[tid * TOPN + ptr]; ci = si[tid * TOPN + ptr]; }
        else { cv = -FLT_MAX; ci = 0x7fffffff; }
        rv[tid] = cv; ri[tid] = ci; rt[tid] = tid;
        __syncthreads();
        for (int o = 128; o > 0; o >>= 1) {
            if (tid < o && better(rv[tid + o], ri[tid + o], rv[tid], ri[tid])) {
                rv[tid] = rv[tid + o]; ri[tid] = ri[tid + o]; rt[tid] = rt[tid + o];
            }
            __syncthreads();
        }
        float wv = rv[0]; int wi = ri[0]; int wt = rt[0];
        __syncthreads();
        if (tid == wt) ptr++;
        if (tid == 0) { topv[k] = wv; topi[k] = wi; }
    }
    __syncthreads();

    if (tid == 0) {
        float sum = 0.f;
        for (int k = 0; k < TOPN; k++) sum += topv[k];
        float u = g_u[(s - 1) * BB + b];
        float c = 0.f; int cnt = 0;
        for (int k = 0; k < TOPN; k++) {
            c += topv[k] / sum;
            if (c < u) cnt++;
        }
        int jj = cnt > (TOPN - 1) ? (TOPN - 1) : cnt;
        int tok = topi[jj];
        g_tok[b] = tok;
        outtok[b * SS + s] = (float)tok;
    }
}

// ---------------- host ----------------
extern "C" void kernel_launch(void* const* d_in, const int* in_sizes, int n_in,
                              void* d_out, int out_size)
{
    const int*   tokens  = (const int*)d_in[0];
    const float* emb1    = (const float*)d_in[1];
    const float* emb2    = (const float*)d_in[2];
    const float* enc1_Wx = (const float*)d_in[3];
    const float* enc1_Wh = (const float*)d_in[4];
    const float* enc1_b  = (const float*)d_in[5];
    const float* enc2_Wx = (const float*)d_in[6];
    const float* enc2_Wh = (const float*)d_in[7];
    const float* enc2_b  = (const float*)d_in[8];
    const float* dec_Wx  = (const float*)d_in[9];
    const float* dec_Wh  = (const float*)d_in[10];
    const float* dec_b   = (const float*)d_in[11];
    const float* Wd      = (const float*)d_in[12];
    const float* bd      = (const float*)d_in[13];
    const int*   start_ptr = (n_in > 15) ? (const int*)d_in[15] : (const int*)0;

    float* out = (float*)d_out;
    float* outtok;
    float* outlog;
    const long LOGN = (long)BB * SS * VV;
    if ((long)out_size >= LOGN + BB * SS) {
        outtok = out;
        outlog = out + BB * SS;
    } else {
        outlog = out;
        cudaGetSymbolAddress((void**)&outtok, g_tokf);
    }

    prep_misc_k<<<2, 512>>>();
    prep_encW_k<<<8192, 256>>>(enc1_Wh, enc2_Wh);
    prep_decW_k<<<8192, 256>>>(dec_Wx, dec_Wh);
    embed_k<<<dim3(BB * TT, 2), 256>>>(tokens, emb1, emb2);

    for (int l = 0; l < 2; l++) {
        gemm_bt_k<<<dim3(32, 8, 2), 256>>>(enc1_Wx + (size_t)l * EE * GG,
                                           enc2_Wx + (size_t)l * EE * GG,
                                           enc1_b + (size_t)l * GG,
                                           enc2_b + (size_t)l * GG, l);
        zero_enc_k<<<256, 256>>>();
        for (int t = 0; t < TT; t++)
            enc_step_k<<<dim3(64, 2), 128>>>(t, l);
        blend_k<<<1, 1024>>>(l);
    }

    for (int s = 0; s < SS; s++) {
        dembedT_k<<<128, 256>>>(emb1, start_ptr, s == 0 ? 1 : 0);
        dec_cell_k<<<128, 128>>>(s, 0, dec_b);
        dec_cell_k<<<128, 128>>>(s, 1, dec_b);
        logits_k<<<250, 256>>>(Wd, bd, outlog, s);
        sample_k<<<BB, 256>>>(outlog, outtok, s);
    }
}

// round 17
// speedup vs baseline: 1.2006x; 1.2006x over previous
#include <cuda_runtime.h>
#include <math.h>
#include <float.h>

#define BB 32
#define TT 32
#define EE 1024
#define HHH 1024
#define GG 4096
#define VV 32000
#define SS 20
#define TOPN 10

// ---------------- device scratch ----------------
__device__ __align__(16) float g_x[2 * 2 * BB * TT * EE];    // [enc][buf][B*T][E]
__device__ __align__(16) float g_z[2 * BB * TT * GG];        // [enc][B*T][4H]
__device__ __align__(16) float g_hT[2 * 2 * HHH * BB];       // [enc][parity][H][B]
__device__ __align__(16) float g_cn[2 * BB * HHH];           // [enc][B][H]
__device__ __align__(16) float g_Whp[2 * 2 * HHH * GG];      // [enc][l][k][c*4+g]
__device__ __align__(16) float g_dWp[2 * 2048 * GG];         // [l][k(0..2047)][c*4+g]
__device__ __align__(16) float g_dhT[2 * 2 * HHH * BB];      // [l][parity][H][B]
__device__ __align__(16) float g_dcn[2 * BB * HHH];          // [l][B][H]
__device__ __align__(16) float g_dxT[EE * BB];               // [E][B]
__device__ int   g_tok[BB];
__device__ float g_u[(SS - 1) * BB];
__device__ float g_tokf[BB * SS];                            // fallback token sink

__device__ __forceinline__ float sigm(float x) { return 1.0f / (1.0f + expf(-x)); }

// ---------------- threefry2x32 core (bit-exact JAX) ----------------
__device__ __forceinline__ void tf2x32(unsigned k0, unsigned k1, unsigned x0, unsigned x1,
                                       unsigned& o0, unsigned& o1)
{
    unsigned ks2 = k0 ^ k1 ^ 0x1BD11BDAu;
    x0 += k0; x1 += k1;
#define TFR(r) { x0 += x1; x1 = (x1 << (r)) | (x1 >> (32 - (r))); x1 ^= x0; }
    TFR(13) TFR(15) TFR(26) TFR(6)   x0 += k1;  x1 += ks2 + 1u;
    TFR(17) TFR(29) TFR(16) TFR(24)  x0 += ks2; x1 += k0 + 2u;
    TFR(13) TFR(15) TFR(26) TFR(6)   x0 += k0;  x1 += k1 + 3u;
    TFR(17) TFR(29) TFR(16) TFR(24)  x0 += k1;  x1 += ks2 + 4u;
    TFR(13) TFR(15) TFR(26) TFR(6)   x0 += ks2; x1 += k0 + 5u;
#undef TFR
    o0 = x0; o1 = x1;
}

// Partitionable-mode (JAX >= 0.4.30 default) key-split + 32-bit random_bits.
__global__ void prep_misc_k()
{
    int t = blockIdx.x * blockDim.x + threadIdx.x;
    if (t < (SS - 1) * BB) {
        int s = t >> 5, b = t & 31;
        unsigned k0, k1;
        tf2x32(0u, 1u, 0u, (unsigned)s, k0, k1);   // key for scan step s (key(1) = (0,1))
        unsigned o0, o1;
        tf2x32(k0, k1, 0u, (unsigned)b, o0, o1);
        unsigned bits = o0 ^ o1;
        g_u[t] = __uint_as_float((bits >> 9) | 0x3f800000u) - 1.0f;
    }
}

// ---------------- weight preprocessing (coalesced gate-interleave) ----------------
// One block per destination row; stage source row in smem, permute, write coalesced.
__global__ void __launch_bounds__(256) prep_encW_k(const float* __restrict__ Wh1,
                                                   const float* __restrict__ Wh2)
{
    int row = blockIdx.x;                     // enc*2048 + l*1024 + k  (4096 rows)
    int k = row & 1023, l = (row >> 10) & 1, enc = row >> 11;
    const float* W = enc ? Wh2 : Wh1;
    const float* src = W + ((size_t)l * HHH + k) * GG;
    float* dst = g_Whp + (size_t)row * GG;
    __shared__ float s[GG];
    for (int i = threadIdx.x; i < GG; i += 256) s[i] = src[i];
    __syncthreads();
    for (int d = threadIdx.x; d < GG; d += 256) {
        int c = d >> 2, g = d & 3;
        dst[d] = s[g * HHH + c];
    }
}

__global__ void __launch_bounds__(256) prep_decW_k(const float* __restrict__ dWx,
                                                   const float* __restrict__ dWh)
{
    int row = blockIdx.x;                     // l*2048 + k2  (4096 rows)
    int k2 = row & 2047, l = row >> 11;
    const float* src = (k2 < 1024) ? (dWx + ((size_t)l * EE + k2) * GG)
                                   : (dWh + ((size_t)l * HHH + (k2 - 1024)) * GG);
    float* dst = g_dWp + (size_t)row * GG;
    __shared__ float s[GG];
    for (int i = threadIdx.x; i < GG; i += 256) s[i] = src[i];
    __syncthreads();
    for (int d = threadIdx.x; d < GG; d += 256) {
        int c = d >> 2, g = d & 3;
        dst[d] = s[g * HHH + c];
    }
}

// ---------------- encoder embedding gather ----------------
__global__ void embed_k(const int* __restrict__ tokens, const float* __restrict__ emb1,
                        const float* __restrict__ emb2)
{
    int bt = blockIdx.x, enc = blockIdx.y;
    int tok = tokens[bt];
    const float4* src = (const float4*)((enc ? emb2 : emb1) + (size_t)tok * EE);
    float4* dst = (float4*)(g_x + ((size_t)enc * 2) * (BB * TT * EE) + (size_t)bt * EE);
    dst[threadIdx.x] = src[threadIdx.x];   // 256 thr * float4 = 1024
}

__global__ void zero_enc_k()
{
    int idx = blockIdx.x * blockDim.x + threadIdx.x;    // < 65536
    if (idx < 2 * HHH * BB) {
        int enc = idx >> 15, off = idx & 32767;
        g_hT[(enc * 2 + 0) * (HHH * BB) + off] = 0.f;
        g_cn[enc * (BB * HHH) + off] = 0.f;
    }
}

// ---------------- big GEMM: z[enc] = X @ Wx + b  (M=1024,K=1024,N=4096) ----------------
__global__ void __launch_bounds__(256) gemm_bt_k(
    const float* __restrict__ Wx1, const float* __restrict__ Wx2,
    const float* __restrict__ b1, const float* __restrict__ b2, int l)
{
    const int enc = blockIdx.z;
    const float* A = g_x + ((size_t)enc * 2 + (l & 1)) * (BB * TT * EE);
    const float* W = enc ? Wx2 : Wx1;
    const float* bias = enc ? b2 : b1;
    float* C = g_z + (size_t)enc * (BB * TT * GG);
    const int K = EE, N = GG;

    __shared__ __align__(16) float As[8][132];
    __shared__ __align__(16) float Bs[8][128];
    int bm = blockIdx.y * 128, bn = blockIdx.x * 128;
    int tid = threadIdx.x;
    int ty = tid >> 4, tx = tid & 15;
    float acc[8][8];
#pragma unroll
    for (int i = 0; i < 8; i++)
#pragma unroll
        for (int j = 0; j < 8; j++) acc[i][j] = 0.f;

    int ar = tid >> 1, ac = (tid & 1) * 4;
    int br = tid >> 5, bc = (tid & 31) * 4;

    for (int k0 = 0; k0 < K; k0 += 8) {
        float4 av = *(const float4*)(A + (size_t)(bm + ar) * K + k0 + ac);
        As[ac + 0][ar] = av.x; As[ac + 1][ar] = av.y; As[ac + 2][ar] = av.z; As[ac + 3][ar] = av.w;
        *(float4*)&Bs[br][bc] = *(const float4*)(W + (size_t)(k0 + br) * N + bn + bc);
        __syncthreads();
#pragma unroll
        for (int kk = 0; kk < 8; kk++) {
            float a[8], bw[8];
            *(float4*)(a)     = *(const float4*)&As[kk][ty * 8];
            *(float4*)(a + 4) = *(const float4*)&As[kk][ty * 8 + 4];
            *(float4*)(bw)    = *(const float4*)&Bs[kk][tx * 8];
            *(float4*)(bw + 4)= *(const float4*)&Bs[kk][tx * 8 + 4];
#pragma unroll
            for (int i = 0; i < 8; i++)
#pragma unroll
                for (int j = 0; j < 8; j++) acc[i][j] = fmaf(a[i], bw[j], acc[i][j]);
        }
        __syncthreads();
    }
    float bv[8];
#pragma unroll
    for (int j = 0; j < 8; j++) bv[j] = bias[bn + tx * 8 + j];
    for (int i = 0; i < 8; i++) {
        float* crow = C + (size_t)(bm + ty * 8 + i) * N + bn + tx * 8;
#pragma unroll
        for (int j = 0; j < 8; j++) crow[j] = acc[i][j] + bv[j];
    }
}

// ---------------- encoder recurrent step, K-split x2 ----------------
// grid (64, 2enc), block 256.  16 h-cols/block; two 128-thread halves each do K/2=512,
// then smem-reduce + fused LSTM gate epilogue.
__global__ void __launch_bounds__(256) enc_step_k(int t, int l)
{
    const int enc = blockIdx.y;
    const int c0 = blockIdx.x * 16;
    const int tid = threadIdx.x;
    const int z = tid >> 7;          // K-half
    const int t2 = tid & 127;
    const int rg = t2 >> 4;          // 8 groups of 4 rows
    const int j = t2 & 15;           // h-col within tile
    const int p = t & 1;
    const int ob = (l & 1) ^ 1;

    __shared__ __align__(16) float hs[2][32 * 32];
    __shared__ __align__(16) float ws[2][32 * 64];
    __shared__ __align__(16) float red[2048];

    float acc[4][4];
#pragma unroll
    for (int r = 0; r < 4; r++)
#pragma unroll
        for (int g = 0; g < 4; g++) acc[r][g] = 0.f;

    const float* hbase = g_hT + (size_t)(enc * 2 + p) * (HHH * BB) + (size_t)z * 512 * BB;
    const float* wbase = g_Whp + ((size_t)(enc * 2 + l) * HHH + z * 512) * GG + c0 * 4;

    for (int k0 = 0; k0 < 512; k0 += 32) {
        const float4* hsrc = (const float4*)(hbase + k0 * BB);
        ((float4*)hs[z])[t2 * 2]     = hsrc[t2 * 2];
        ((float4*)hs[z])[t2 * 2 + 1] = hsrc[t2 * 2 + 1];
        const float* wsrc = wbase + (size_t)k0 * GG;
#pragma unroll
        for (int u = 0; u < 4; u++) {
            int idx = t2 + u * 128;
            int kk = idx >> 4, cc = (idx & 15) * 4;
            *(float4*)&ws[z][kk * 64 + cc] = *(const float4*)&wsrc[(size_t)kk * GG + cc];
        }
        __syncthreads();
#pragma unroll
        for (int kk = 0; kk < 32; kk++) {
            float4 a4 = *(const float4*)&hs[z][kk * 32 + rg * 4];
            float4 w4 = *(const float4*)&ws[z][kk * 64 + j * 4];
            float a[4] = {a4.x, a4.y, a4.z, a4.w};
            float w[4] = {w4.x, w4.y, w4.z, w4.w};
#pragma unroll
            for (int r = 0; r < 4; r++)
#pragma unroll
                for (int g = 0; g < 4; g++) acc[r][g] = fmaf(a[r], w[g], acc[r][g]);
        }
        __syncthreads();
    }

    // reduce the two K-halves
    if (z == 1) {
#pragma unroll
        for (int r = 0; r < 4; r++)
#pragma unroll
            for (int g = 0; g < 4; g++)
                red[(rg * 4 + r) * 64 + j * 4 + g] = acc[r][g];
    }
    __syncthreads();
    if (z == 0) {
        const float* zbase = g_z + (size_t)enc * (BB * TT * GG);
        float* hTout = g_hT + (size_t)(enc * 2 + (p ^ 1)) * (HHH * BB);
        float* xout = g_x + ((size_t)enc * 2 + ob) * (BB * TT * EE);
        float* cbase = g_cn + (size_t)enc * (BB * HHH);
        const int col = c0 + j;
#pragma unroll
        for (int r = 0; r < 4; r++) {
            int b = rg * 4 + r;
            int m = b * TT + t;
            const float* zr = zbase + (size_t)m * GG;
            float s0 = acc[r][0] + red[b * 64 + j * 4 + 0];
            float s1 = acc[r][1] + red[b * 64 + j * 4 + 1];
            float s2 = acc[r][2] + red[b * 64 + j * 4 + 2];
            float s3 = acc[r][3] + red[b * 64 + j * 4 + 3];
            float zi = zr[0 * HHH + col] + s0;
            float zf = zr[1 * HHH + col] + s1;
            float zg = zr[2 * HHH + col] + s2;
            float zo = zr[3 * HHH + col] + s3;
            float co = cbase[b * HHH + col];
            float cnw = sigm(zf) * co + sigm(zi) * tanhf(zg);
            float hn = sigm(zo) * tanhf(cnw);
            cbase[b * HHH + col] = cnw;
            hTout[col * BB + b] = hn;
            xout[(size_t)m * EE + col] = hn;
        }
    }
}

// ---------------- blend + global L2 normalize -> decoder init states ----------------
__global__ void blend_k(int l)
{
    __shared__ float red[1024];
    __shared__ float s_inv;
    int tid = threadIdx.x;
    const int N = HHH * BB;

    float loc = 0.f;
    for (int i = tid; i < N; i += 1024) {
        float v = g_hT[i] + 2.0f * g_hT[2 * N + i];
        loc += v * v;
    }
    red[tid] = loc; __syncthreads();
    for (int o = 512; o > 0; o >>= 1) { if (tid < o) red[tid] += red[tid + o]; __syncthreads(); }
    if (tid == 0) s_inv = 1.0f / (sqrtf(red[0]) + 1e-12f);
    __syncthreads();
    float inv = s_inv;
    for (int i = tid; i < N; i += 1024) {
        float v = g_hT[i] + 2.0f * g_hT[2 * N + i];
        g_dhT[(l * 2 + 0) * N + i] = v * inv;
    }
    __syncthreads();

    loc = 0.f;
    for (int i = tid; i < N; i += 1024) {
        float v = g_cn[i] + 2.0f * g_cn[N + i];
        loc += v * v;
    }
    red[tid] = loc; __syncthreads();
    for (int o = 512; o > 0; o >>= 1) { if (tid < o) red[tid] += red[tid + o]; __syncthreads(); }
    if (tid == 0) s_inv = 1.0f / (sqrtf(red[0]) + 1e-12f);
    __syncthreads();
    inv = s_inv;
    for (int i = tid; i < N; i += 1024) {
        float v = g_cn[i] + 2.0f * g_cn[N + i];
        g_dcn[l * N + i] = v * inv;
    }
}

// ---------------- decoder embedding gather (transposed) ----------------
__global__ void dembedT_k(const float* __restrict__ emb1, const int* __restrict__ start_ptr,
                          int use_start)
{
    int idx = blockIdx.x * blockDim.x + threadIdx.x;   // < 32768
    if (idx < EE * BB) {
        int b = idx & 31, k = idx >> 5;
        int tok = use_start ? (start_ptr ? start_ptr[0] : 1) : g_tok[b];
        g_dxT[k * BB + b] = emb1[(size_t)tok * EE + k];
    }
}

// ---------------- decoder LSTM cell, K-split x2 (x-half / h-half) ----------------
// grid 128, block 256.  8 h-cols/block; half z=0 does x@Wx (k 0..1023),
// half z=1 does h@Wh (k 1024..2047); smem-reduce + gate epilogue.
__global__ void __launch_bounds__(256) dec_cell_k(int s, int l, const float* __restrict__ bias_all)
{
    const int c0 = blockIdx.x * 8;
    const int tid = threadIdx.x;
    const int z = tid >> 7;
    const int t2 = tid & 127;
    const int rg = t2 >> 3;      // 16 groups of 2 rows
    const int j = t2 & 7;        // h-col within tile
    const int ps = s & 1;
    const int N = HHH * BB;

    __shared__ __align__(16) float hs[2][32 * 32];
    __shared__ __align__(16) float ws[2][32 * 32];
    __shared__ __align__(16) float red[1024];

    float acc[2][4];
#pragma unroll
    for (int r = 0; r < 2; r++)
#pragma unroll
        for (int g = 0; g < 4; g++) acc[r][g] = 0.f;

    const float* xT = (l == 0) ? g_dxT : (g_dhT + (size_t)(0 * 2 + (ps ^ 1)) * N);
    const float* hT = g_dhT + (size_t)(l * 2 + ps) * N;
    const float* abase = z ? hT : xT;
    const float* wbase = g_dWp + ((size_t)l * 2048 + z * 1024) * GG + c0 * 4;

    for (int k0 = 0; k0 < 1024; k0 += 32) {
        const float4* asrc = (const float4*)(abase + k0 * BB);
        ((float4*)hs[z])[t2 * 2]     = asrc[t2 * 2];
        ((float4*)hs[z])[t2 * 2 + 1] = asrc[t2 * 2 + 1];
        const float* wsrc = wbase + (size_t)k0 * GG;
#pragma unroll
        for (int u = 0; u < 2; u++) {
            int idx = t2 + u * 128;
            int kk = idx >> 3, cc = (idx & 7) * 4;
            *(float4*)&ws[z][kk * 32 + cc] = *(const float4*)&wsrc[(size_t)kk * GG + cc];
        }
        __syncthreads();
#pragma unroll
        for (int kk = 0; kk < 32; kk++) {
            float2 a2 = *(const float2*)&hs[z][kk * 32 + rg * 2];
            float4 w4 = *(const float4*)&ws[z][kk * 32 + j * 4];
            float w[4] = {w4.x, w4.y, w4.z, w4.w};
#pragma unroll
            for (int g = 0; g < 4; g++) {
                acc[0][g] = fmaf(a2.x, w[g], acc[0][g]);
                acc[1][g] = fmaf(a2.y, w[g], acc[1][g]);
            }
        }
        __syncthreads();
    }

    if (z == 1) {
#pragma unroll
        for (int r = 0; r < 2; r++)
#pragma unroll
            for (int g = 0; g < 4; g++)
                red[(rg * 2 + r) * 32 + j * 4 + g] = acc[r][g];
    }
    __syncthreads();
    if (z == 0) {
        const float* bias = bias_all + (size_t)l * GG;
        float* hTout = g_dhT + (size_t)(l * 2 + (ps ^ 1)) * N;
        float* cbase = g_dcn + (size_t)l * N;
        const int col = c0 + j;
#pragma unroll
        for (int r = 0; r < 2; r++) {
            int b = rg * 2 + r;
            float zi = acc[r][0] + red[b * 32 + j * 4 + 0] + bias[0 * HHH + col];
            float zf = acc[r][1] + red[b * 32 + j * 4 + 1] + bias[1 * HHH + col];
            float zg = acc[r][2] + red[b * 32 + j * 4 + 2] + bias[2 * HHH + col];
            float zo = acc[r][3] + red[b * 32 + j * 4 + 3] + bias[3 * HHH + col];
            float co = cbase[b * HHH + col];
            float cnw = sigm(zf) * co + sigm(zi) * tanhf(zg);
            float hn = sigm(zo) * tanhf(cnw);
            cbase[b * HHH + col] = cnw;
            hTout[col * BB + b] = hn;
        }
    }
}

// ---------------- logits GEMM: [32,1024] x [1024,32000] + bd ----------------
__global__ void __launch_bounds__(256) logits_k(const float* __restrict__ Wd,
                                                const float* __restrict__ bd,
                                                float* __restrict__ outlog, int s)
{
    const int n0 = blockIdx.x * 128;
    const int tid = threadIdx.x;
    const int rg = tid >> 5;     // 0..7 -> rows rg*4
    const int cg = tid & 31;     // cols cg*4

    __shared__ __align__(16) float As[32 * 32];
    __shared__ __align__(16) float Bs[32 * 128];

    const float* A = g_dhT + (size_t)(1 * 2 + ((s & 1) ^ 1)) * (HHH * BB);

    float acc[4][4];
#pragma unroll
    for (int r = 0; r < 4; r++)
#pragma unroll
        for (int c = 0; c < 4; c++) acc[r][c] = 0.f;

    for (int k0 = 0; k0 < HHH; k0 += 32) {
        ((float4*)As)[tid] = ((const float4*)(A + k0 * BB))[tid];
        const float* wsrc = Wd + (size_t)k0 * VV + n0;
#pragma unroll
        for (int u = 0; u < 4; u++) {
            int idx = tid + u * 256;
            int kk = idx >> 5, cc = (idx & 31) * 4;
            *(float4*)&Bs[kk * 128 + cc] = *(const float4*)&wsrc[(size_t)kk * VV + cc];
        }
        __syncthreads();
#pragma unroll
        for (int kk = 0; kk < 32; kk++) {
            float4 a4 = *(const float4*)&As[kk * 32 + rg * 4];
            float4 b4 = *(const float4*)&Bs[kk * 128 + cg * 4];
            float a[4] = {a4.x, a4.y, a4.z, a4.w};
            float bw[4] = {b4.x, b4.y, b4.z, b4.w};
#pragma unroll
            for (int r = 0; r < 4; r++)
#pragma unroll
                for (int c = 0; c < 4; c++) acc[r][c] = fmaf(a[r], bw[c], acc[r][c]);
        }
        __syncthreads();
    }

    const int nb = n0 + cg * 4;
    float4 bv = *(const float4*)&bd[nb];
    float bwv[4] = {bv.x, bv.y, bv.z, bv.w};
#pragma unroll
    for (int r = 0; r < 4; r++) {
        int b = rg * 4 + r;
        float4 o;
        o.x = acc[r][0] + bwv[0];
        o.y = acc[r][1] + bwv[1];
        o.z = acc[r][2] + bwv[2];
        o.w = acc[r][3] + bwv[3];
        *(float4*)&outlog[((size_t)b * SS + s) * VV + nb] = o;
    }
}

// ---------------- argmax / top-10 sampling ----------------
__device__ __forceinline__ bool better(float v1, int i1, float v2, int i2)
{
    return (v1 > v2) || (v1 == v2 && i1 < i2);
}

__global__ void sample_k(const float* __restrict__ outlog, float* __restrict__ outtok, int s)
{
    const int b = blockIdx.x;
    const int tid = threadIdx.x;
    const float* lg = outlog + ((size_t)b * SS + s) * VV;

    __shared__ float rv[256];
    __shared__ int ri[256];
    __shared__ int rt[256];

    if (s == 0) {
        float bv = -FLT_MAX; int bi = 0x7fffffff;
        for (int n = tid; n < VV; n += 256) {
            float v = lg[n];
            if (better(v, n, bv, bi)) { bv = v; bi = n; }
        }
        rv[tid] = bv; ri[tid] = bi;
        __syncthreads();
        for (int o = 128; o > 0; o >>= 1) {
            if (tid < o && better(rv[tid + o], ri[tid + o], rv[tid], ri[tid])) {
                rv[tid] = rv[tid + o]; ri[tid] = ri[tid + o];
            }
            __syncthreads();
        }
        if (tid == 0) {
            g_tok[b] = ri[0];
            outtok[b * SS + 0] = (float)ri[0];
        }
        return;
    }

    __shared__ float sv[256 * TOPN];
    __shared__ int si[256 * TOPN];
    __shared__ float topv[TOPN];
    __shared__ int topi[TOPN];

    float lv[TOPN]; int li[TOPN];
#pragma unroll
    for (int k = 0; k < TOPN; k++) { lv[k] = -FLT_MAX; li[k] = 0x7fffffff; }
    for (int n = tid; n < VV; n += 256) {
        float v = lg[n];
        if (better(v, n, lv[TOPN - 1], li[TOPN - 1])) {
            int k = TOPN - 1;
            while (k > 0 && better(v, n, lv[k - 1], li[k - 1])) {
                lv[k] = lv[k - 1]; li[k] = li[k - 1]; k--;
            }
            lv[k] = v; li[k] = n;
        }
    }
#pragma unroll
    for (int k = 0; k < TOPN; k++) { sv[tid * TOPN + k] = lv[k]; si[tid * TOPN + k] = li[k]; }

    int ptr = 0;
    for (int k = 0; k < TOPN; k++) {
        float cv; int ci;
        if (ptr < TOPN) { cv = sv[tid * TOPN + ptr]; ci = si[tid * TOPN + ptr]; }
        else { cv = -FLT_MAX; ci = 0x7fffffff; }
        rv[tid] = cv; ri[tid] = ci; rt[tid] = tid;
        __syncthreads();
        for (int o = 128; o > 0; o >>= 1) {
            if (tid < o && better(rv[tid + o], ri[tid + o], rv[tid], ri[tid])) {
                rv[tid] = rv[tid + o]; ri[tid] = ri[tid + o]; rt[tid] = rt[tid + o];
            }
            __syncthreads();
        }
        float wv = rv[0]; int wi = ri[0]; int wt = rt[0];
        __syncthreads();
        if (tid == wt) ptr++;
        if (tid == 0) { topv[k] = wv; topi[k] = wi; }
    }
    __syncthreads();

    if (tid == 0) {
        float sum = 0.f;
        for (int k = 0; k < TOPN; k++) sum += topv[k];
        float u = g_u[(s - 1) * BB + b];
        float c = 0.f; int cnt = 0;
        for (int k = 0; k < TOPN; k++) {
            c += topv[k] / sum;
            if (c < u) cnt++;
        }
        int jj = cnt > (TOPN - 1) ? (TOPN - 1) : cnt;
        int tok = topi[jj];
        g_tok[b] = tok;
        outtok[b * SS + s] = (float)tok;
    }
}

// ---------------- host ----------------
extern "C" void kernel_launch(void* const* d_in, const int* in_sizes, int n_in,
                              void* d_out, int out_size)
{
    const int*   tokens  = (const int*)d_in[0];
    const float* emb1    = (const float*)d_in[1];
    const float* emb2    = (const float*)d_in[2];
    const float* enc1_Wx = (const float*)d_in[3];
    const float* enc1_Wh = (const float*)d_in[4];
    const float* enc1_b  = (const float*)d_in[5];
    const float* enc2_Wx = (const float*)d_in[6];
    const float* enc2_Wh = (const float*)d_in[7];
    const float* enc2_b  = (const float*)d_in[8];
    const float* dec_Wx  = (const float*)d_in[9];
    const float* dec_Wh  = (const float*)d_in[10];
    const float* dec_b   = (const float*)d_in[11];
    const float* Wd      = (const float*)d_in[12];
    const float* bd      = (const float*)d_in[13];
    const int*   start_ptr = (n_in > 15) ? (const int*)d_in[15] : (const int*)0;

    float* out = (float*)d_out;
    float* outtok;
    float* outlog;
    const long LOGN = (long)BB * SS * VV;
    if ((long)out_size >= LOGN + BB * SS) {
        outtok = out;
        outlog = out + BB * SS;
    } else {
        outlog = out;
        cudaGetSymbolAddress((void**)&outtok, g_tokf);
    }

    prep_misc_k<<<2, 512>>>();
    prep_encW_k<<<4096, 256>>>(enc1_Wh, enc2_Wh);
    prep_decW_k<<<4096, 256>>>(dec_Wx, dec_Wh);
    embed_k<<<dim3(BB * TT, 2), 256>>>(tokens, emb1, emb2);

    for (int l = 0; l < 2; l++) {
        gemm_bt_k<<<dim3(32, 8, 2), 256>>>(enc1_Wx + (size_t)l * EE * GG,
                                           enc2_Wx + (size_t)l * EE * GG,
                                           enc1_b + (size_t)l * GG,
                                           enc2_b + (size_t)l * GG, l);
        zero_enc_k<<<256, 256>>>();
        for (int t = 0; t < TT; t++)
            enc_step_k<<<dim3(64, 2), 256>>>(t, l);
        blend_k<<<1, 1024>>>(l);
    }

    for (int s = 0; s < SS; s++) {
        dembedT_k<<<128, 256>>>(emb1, start_ptr, s == 0 ? 1 : 0);
        dec_cell_k<<<128, 256>>>(s, 0, dec_b);
        dec_cell_k<<<128, 256>>>(s, 1, dec_b);
        logits_k<<<250, 256>>>(Wd, bd, outlog, s);
        sample_k<<<BB, 256>>>(outlog, outtok, s);
    }
}